// round 3
// baseline (speedup 1.0000x reference)
#include <cuda_runtime.h>
#include <math.h>

#define NN   100000
#define EE   3200000
#define PPAIR 1000000
#define EMB  32
#define HID  64
#define PATF 8

// ---------------- scratch (device globals: allocation-free) ----------------
__device__ float g_deg[NN];
__device__ float g_dinv[NN];
__device__ __align__(128) float g_agg0[NN * EMB];  // aggregated (init = self loop)
__device__ __align__(128) float g_s1[NN * HID];    // relu(x1) * dinv
__device__ __align__(128) float g_agg1[NN * HID];
__device__ __align__(128) float g_x2[NN * HID];    // layer-2 output

// ---------------- helpers ----------------
__device__ __forceinline__ void red_add_v4(float* addr, float4 v) {
    asm volatile("red.global.add.v4.f32 [%0], {%1,%2,%3,%4};"
                 :: "l"(addr), "f"(v.x), "f"(v.y), "f"(v.z), "f"(v.w)
                 : "memory");
}
__device__ __forceinline__ unsigned long long pack2_dup(float x) {
    unsigned long long d; unsigned r = __float_as_uint(x);
    asm("mov.b64 %0, {%1, %1};" : "=l"(d) : "r"(r));
    return d;
}
__device__ __forceinline__ unsigned long long fma2(unsigned long long a,
                                                   unsigned long long b,
                                                   unsigned long long c) {
    unsigned long long d;
    asm("fma.rn.f32x2 %0, %1, %2, %3;" : "=l"(d) : "l"(a), "l"(b), "l"(c));
    return d;
}
__device__ __forceinline__ float2 unpack2(unsigned long long a) {
    unsigned lo, hi;
    asm("mov.b64 {%0, %1}, %2;" : "=r"(lo), "=r"(hi) : "l"(a));
    return make_float2(__uint_as_float(lo), __uint_as_float(hi));
}

// ---------------- degree ----------------
__global__ void k_deg_init() {
    int i = blockIdx.x * blockDim.x + threadIdx.x;
    if (i < NN) g_deg[i] = 1.0f;   // self loop
}
__global__ void k_deg_count(const int* __restrict__ dst) {
    int e = blockIdx.x * blockDim.x + threadIdx.x;
    if (e < EE) atomicAdd(&g_deg[__ldg(dst + e)], 1.0f);
}
__global__ void k_dinv() {
    int i = blockIdx.x * blockDim.x + threadIdx.x;
    if (i < NN) g_dinv[i] = rsqrtf(g_deg[i]);   // deg >= 1 always
}

// agg0 init = emb * dinv (self loop contribution, norm = dinv*dinv later folded)
__global__ void k_prep0(const float* __restrict__ emb) {
    int t = blockIdx.x * blockDim.x + threadIdx.x;
    if (t >= NN * (EMB / 4)) return;
    int node = t >> 3;            // EMB/4 = 8 chunks
    float di = g_dinv[node];
    float4 v = ((const float4*)emb)[t];
    v.x *= di; v.y *= di; v.z *= di; v.w *= di;
    ((float4*)g_agg0)[t] = v;
}

// ---------------- edge scatter (vector reductions) ----------------
// thread = (edge, chunk). Adjacent threads share edge -> index/dinv loads are
// L1-broadcast; float4 src reads are contiguous per edge; red.v4 hits a
// distinct 16B address per thread (no same-address serialization within edge).
__global__ void k_scatter0(const int* __restrict__ src, const int* __restrict__ dst,
                           const float* __restrict__ emb) {
    long long t = (long long)blockIdx.x * blockDim.x + threadIdx.x;
    if (t >= (long long)EE * (EMB / 4)) return;
    int e = (int)(t >> 3);
    int c = (int)(t & 7);
    int s = __ldg(src + e), d = __ldg(dst + e);
    float di = __ldg(g_dinv + s);                 // fold dinv[src] here
    float4 v = ((const float4*)emb)[s * (EMB / 4) + c];
    v.x *= di; v.y *= di; v.z *= di; v.w *= di;
    red_add_v4(g_agg0 + d * EMB + c * 4, v);
}
__global__ void k_scatter1(const int* __restrict__ src, const int* __restrict__ dst) {
    long long t = (long long)blockIdx.x * blockDim.x + threadIdx.x;
    if (t >= (long long)EE * (HID / 4)) return;
    int e = (int)(t >> 4);
    int c = (int)(t & 15);
    int s = __ldg(src + e), d = __ldg(dst + e);
    float4 v = ((const float4*)g_s1)[s * (HID / 4) + c];   // dinv[src] pre-folded
    red_add_v4(g_agg1 + d * HID + c * 4, v);
}

// ---------------- layer 1: x1 = relu((dinv*agg0) @ W1 + b1); s1 = x1*dinv ----------------
// warp per node; lane computes outputs lane and lane+32
__global__ void k_layer1(const float* __restrict__ W1, const float* __restrict__ b1) {
    __shared__ float sW[EMB * HID];
    __shared__ float sb[HID];
    int tid = threadIdx.x;
    for (int i = tid; i < EMB * HID; i += blockDim.x) sW[i] = W1[i];
    if (tid < HID) sb[tid] = b1[tid];
    __syncthreads();

    int warp = tid >> 5, lane = tid & 31;
    int node = blockIdx.x * (blockDim.x >> 5) + warp;
    if (node >= NN) return;
    float di = g_dinv[node];
    float a = g_agg0[node * EMB + lane] * di;   // lane holds a[lane]
    float acc0 = sb[lane], acc1 = sb[lane + 32];
#pragma unroll
    for (int c = 0; c < EMB; c++) {
        float ac = __shfl_sync(0xffffffffu, a, c);
        acc0 = fmaf(ac, sW[c * HID + lane], acc0);
        acc1 = fmaf(ac, sW[c * HID + lane + 32], acc1);
    }
    float v0 = fmaxf(acc0, 0.0f) * di;
    float v1 = fmaxf(acc1, 0.0f) * di;
    g_s1[node * HID + lane]        = v0;
    g_s1[node * HID + lane + 32]   = v1;
    g_agg1[node * HID + lane]      = v0;   // self loop init
    g_agg1[node * HID + lane + 32] = v1;
}

// ---------------- layer 2: x2 = (dinv*agg1) @ W2 + b2 (no relu) ----------------
__global__ void k_layer2(const float* __restrict__ W2, const float* __restrict__ b2) {
    __shared__ float sW[HID * HID];
    __shared__ float sb[HID];
    int tid = threadIdx.x;
    for (int i = tid; i < HID * HID; i += blockDim.x) sW[i] = W2[i];
    if (tid < HID) sb[tid] = b2[tid];
    __syncthreads();

    int warp = tid >> 5, lane = tid & 31;
    int node = blockIdx.x * (blockDim.x >> 5) + warp;
    if (node >= NN) return;
    float di = g_dinv[node];
    float a0 = g_agg1[node * HID + lane] * di;
    float a1 = g_agg1[node * HID + lane + 32] * di;
    float acc0 = sb[lane], acc1 = sb[lane + 32];
#pragma unroll
    for (int c = 0; c < 32; c++) {
        float ac = __shfl_sync(0xffffffffu, a0, c);
        acc0 = fmaf(ac, sW[c * HID + lane], acc0);
        acc1 = fmaf(ac, sW[c * HID + lane + 32], acc1);
    }
#pragma unroll
    for (int c = 0; c < 32; c++) {
        float ac = __shfl_sync(0xffffffffu, a1, c);
        acc0 = fmaf(ac, sW[(c + 32) * HID + lane], acc0);
        acc1 = fmaf(ac, sW[(c + 32) * HID + lane + 32], acc1);
    }
    g_x2[node * HID + lane]      = acc0;
    g_x2[node * HID + lane + 32] = acc1;
}

// ---------------- final pair MLP ----------------
// thread per pair; combined vector staged in shared (pad 73 -> conflict-free);
// 72x64 GEMV done with fma.rn.f32x2 (packed fp32 FMA, 2x pipe throughput)
#define FB 128       // pairs per block (== blockDim)
#define CIN 72       // HID + PATF
#define CPAD 73

__global__ void __launch_bounds__(FB, 4)
k_final(const int* __restrict__ pairs,
        const float* __restrict__ pat,
        const float* __restrict__ Wf1, const float* __restrict__ bf1,
        const float* __restrict__ Wf2, const float* __restrict__ bf2,
        float* __restrict__ out) {
    extern __shared__ float sm[];
    float* sW  = sm;                    // 72*64 = 4608
    float* sb1 = sW + CIN * HID;        // 64
    float* sW2 = sb1 + HID;             // 64
    int*   sp  = (int*)(sW2 + HID);     // 2*FB
    float* sc  = (float*)(sp + 2 * FB); // FB * CPAD

    int tid = threadIdx.x;
    int base = blockIdx.x * FB;

    for (int i = tid; i < CIN * HID; i += FB) sW[i] = Wf1[i];
    if (tid < HID) { sb1[tid] = bf1[tid]; sW2[tid] = Wf2[tid]; }
    {
        int p = base + tid;
        if (p < PPAIR) {
            int2 pr = ((const int2*)pairs)[p];
            sp[2 * tid]     = pr.x;
            sp[2 * tid + 1] = pr.y;
        }
    }
    __syncthreads();

    // stage drug*adr into shared (16 chunk-slots per pair, 16 iters/thread)
    for (int idx = tid; idx < FB * (HID / 4); idx += FB) {
        int pp = idx >> 4, c4 = idx & 15;
        if (base + pp < PPAIR) {
            float4 vd = ((const float4*)g_x2)[sp[2 * pp]     * (HID / 4) + c4];
            float4 va = ((const float4*)g_x2)[sp[2 * pp + 1] * (HID / 4) + c4];
            float* d = sc + pp * CPAD + c4 * 4;
            d[0] = vd.x * va.x; d[1] = vd.y * va.y;
            d[2] = vd.z * va.z; d[3] = vd.w * va.w;
        }
    }
    // stage patient features (2 float4 per pair)
    for (int idx = tid; idx < FB * 2; idx += FB) {
        int pp = idx >> 1, h = idx & 1;
        if (base + pp < PPAIR) {
            float4 pv = ((const float4*)pat)[(base + pp) * 2 + h];
            float* d = sc + pp * CPAD + HID + h * 4;
            d[0] = pv.x; d[1] = pv.y; d[2] = pv.z; d[3] = pv.w;
        }
    }
    __syncthreads();

    int p = base + tid;
    if (p >= PPAIR) return;

    unsigned long long acc[HID / 2];
#pragma unroll
    for (int j = 0; j < HID / 2; j++)
        acc[j] = ((const unsigned long long*)sb1)[j];

    const float* c = sc + tid * CPAD;
#pragma unroll 8
    for (int k = 0; k < CIN; k++) {
        unsigned long long ck2 = pack2_dup(c[k]);
        const ulonglong2* wr = (const ulonglong2*)(sW + k * HID);
#pragma unroll
        for (int q = 0; q < HID / 4; q++) {
            ulonglong2 w = wr[q];
            acc[2 * q]     = fma2(ck2, w.x, acc[2 * q]);
            acc[2 * q + 1] = fma2(ck2, w.y, acc[2 * q + 1]);
        }
    }

    float s = bf2[0];
#pragma unroll
    for (int j = 0; j < HID / 2; j++) {
        float2 hv = unpack2(acc[j]);
        s = fmaf(fmaxf(hv.x, 0.0f), sW2[2 * j],     s);
        s = fmaf(fmaxf(hv.y, 0.0f), sW2[2 * j + 1], s);
    }
    out[p] = 1.0f / (1.0f + __expf(-s));
}

// ---------------- launch ----------------
extern "C" void kernel_launch(void* const* d_in, const int* in_sizes, int n_in,
                              void* d_out, int out_size) {
    const int*   edge_index = (const int*)d_in[0];     // (2, E)
    const int*   edge_pairs = (const int*)d_in[1];     // (P, 2)
    const float* pat        = (const float*)d_in[2];   // (P, 8)
    const float* emb        = (const float*)d_in[3];   // (N, 32)
    const float* W1         = (const float*)d_in[4];
    const float* b1         = (const float*)d_in[5];
    const float* W2         = (const float*)d_in[6];
    const float* b2         = (const float*)d_in[7];
    const float* Wf1        = (const float*)d_in[8];
    const float* bf1        = (const float*)d_in[9];
    const float* Wf2        = (const float*)d_in[10];
    const float* bf2        = (const float*)d_in[11];
    float* out = (float*)d_out;

    const int* src = edge_index;
    const int* dst = edge_index + EE;

    // degree + normalization
    k_deg_init<<<(NN + 255) / 256, 256>>>();
    k_deg_count<<<(EE + 255) / 256, 256>>>(dst);
    k_dinv<<<(NN + 255) / 256, 256>>>();

    // layer 1 (aggregate-first: 32-dim messages, dinv[src] folded in scatter)
    k_prep0<<<(NN * (EMB / 4) + 255) / 256, 256>>>(emb);
    {
        long long tot = (long long)EE * (EMB / 4);
        k_scatter0<<<(unsigned)((tot + 255) / 256), 256>>>(src, dst, emb);
    }
    k_layer1<<<(NN + 7) / 8, 256>>>(W1, b1);

    // layer 2 (64-dim messages)
    {
        long long tot = (long long)EE * (HID / 4);
        k_scatter1<<<(unsigned)((tot + 255) / 256), 256>>>(src, dst);
    }
    k_layer2<<<(NN + 3) / 4, 128>>>(W2, b2);

    // final pair MLP
    int smem = (CIN * HID + HID + HID) * 4 + 2 * FB * 4 + FB * CPAD * 4;
    cudaFuncSetAttribute(k_final, cudaFuncAttributeMaxDynamicSharedMemorySize, smem);
    k_final<<<(PPAIR + FB - 1) / FB, FB, smem>>>(edge_pairs, pat, Wf1, bf1, Wf2, bf2, out);

    (void)in_sizes; (void)n_in; (void)out_size;
}

// round 4
// speedup vs baseline: 1.2165x; 1.2165x over previous
#include <cuda_runtime.h>
#include <math.h>

#define NN    100000
#define EE    3200000
#define PPAIR 1000000
#define EMB   32
#define HID   64
#define PATF  8

#define SCAN_B 1024
#define NBLK   ((NN + SCAN_B - 1) / SCAN_B)   // 98

// ---------------- scratch (device globals: allocation-free) ----------------
__device__ int   g_cnt[NN];
__device__ int   g_off[NN];
__device__ int   g_cur[NN];
__device__ int   g_blk[NBLK];
__device__ int   g_nbr[EE];
__device__ float g_dinv[NN];
__device__ __align__(128) float g_s1[NN * HID];   // relu(x1) * dinv
__device__ __align__(128) float g_x2[NN * HID];   // layer-2 output

// ---------------- helpers ----------------
__device__ __forceinline__ unsigned long long pack2_dup(float x) {
    unsigned long long d; unsigned r = __float_as_uint(x);
    asm("mov.b64 %0, {%1, %1};" : "=l"(d) : "r"(r));
    return d;
}
__device__ __forceinline__ unsigned long long fma2(unsigned long long a,
                                                   unsigned long long b,
                                                   unsigned long long c) {
    unsigned long long d;
    asm("fma.rn.f32x2 %0, %1, %2, %3;" : "=l"(d) : "l"(a), "l"(b), "l"(c));
    return d;
}
__device__ __forceinline__ float2 unpack2(unsigned long long a) {
    unsigned lo, hi;
    asm("mov.b64 {%0, %1}, %2;" : "=r"(lo), "=r"(hi) : "l"(a));
    return make_float2(__uint_as_float(lo), __uint_as_float(hi));
}

// ---------------- CSR build ----------------
__global__ void k_zero() {
    int i = blockIdx.x * blockDim.x + threadIdx.x;
    if (i < NN) g_cnt[i] = 0;
}
__global__ void k_hist(const int* __restrict__ dst) {
    int e = blockIdx.x * blockDim.x + threadIdx.x;
    if (e < EE) atomicAdd(&g_cnt[__ldg(dst + e)], 1);
}
// block-level exclusive scan + block totals
__global__ void k_scan1() {
    __shared__ int sh[SCAN_B];
    int t = threadIdx.x;
    int idx = blockIdx.x * SCAN_B + t;
    int v = (idx < NN) ? g_cnt[idx] : 0;
    sh[t] = v; __syncthreads();
#pragma unroll
    for (int d = 1; d < SCAN_B; d <<= 1) {
        int x = (t >= d) ? sh[t - d] : 0;
        __syncthreads();
        sh[t] += x;
        __syncthreads();
    }
    if (idx < NN) g_off[idx] = sh[t] - v;            // exclusive within block
    if (t == SCAN_B - 1) g_blk[blockIdx.x] = sh[t];  // block total
}
__global__ void k_scan2() {   // exclusive scan of 98 block totals, one block
    __shared__ int sh[128];
    int t = threadIdx.x;
    int v = (t < NBLK) ? g_blk[t] : 0;
    sh[t] = v; __syncthreads();
#pragma unroll
    for (int d = 1; d < 128; d <<= 1) {
        int x = (t >= d) ? sh[t - d] : 0;
        __syncthreads();
        sh[t] += x;
        __syncthreads();
    }
    if (t < NBLK) g_blk[t] = sh[t] - v;
}
__global__ void k_scan3() {   // finalize offsets, cursors, dinv
    int i = blockIdx.x * blockDim.x + threadIdx.x;
    if (i >= NN) return;
    int o = g_off[i] + g_blk[i >> 10];
    g_off[i] = o;
    g_cur[i] = o;
    g_dinv[i] = rsqrtf((float)(g_cnt[i] + 1));   // +1 self loop
}
__global__ void k_fill(const int* __restrict__ src, const int* __restrict__ dst) {
    int e = blockIdx.x * blockDim.x + threadIdx.x;
    if (e >= EE) return;
    int d = __ldg(dst + e);
    int pos = atomicAdd(&g_cur[d], 1);
    g_nbr[pos] = __ldg(src + e);
}

// ---------------- fused GCN layer 1 (gather + matmul) ----------------
// warp per node (NPW nodes per warp); lane owns emb column `lane`
#define GB1 512
#define NPW 4
__global__ void __launch_bounds__(GB1)
k_gcn1(const float* __restrict__ emb, const float* __restrict__ W1,
       const float* __restrict__ b1) {
    __shared__ float sW[EMB * HID];
    __shared__ float sb[HID];
    int tid = threadIdx.x;
    for (int i = tid; i < EMB * HID; i += GB1) sW[i] = W1[i];
    if (tid < HID) sb[tid] = b1[tid];
    __syncthreads();

    int warp = tid >> 5, lane = tid & 31;
    int wbase = (blockIdx.x * (GB1 >> 5) + warp) * NPW;
#pragma unroll
    for (int n = 0; n < NPW; n++) {
        int node = wbase + n;
        if (node >= NN) return;
        float din = __ldg(g_dinv + node);
        float acc = __ldg(emb + node * EMB + lane) * din;   // self loop
        int off = g_off[node], cnt = g_cnt[node];
        int nb = cnt & ~31;
        for (int base = 0; base < nb; base += 32) {
            int id = g_nbr[off + base + lane];
#pragma unroll
            for (int k = 0; k < 32; k++) {
                int s = __shfl_sync(0xffffffffu, id, k);
                acc = fmaf(__ldg(emb + s * EMB + lane), __ldg(g_dinv + s), acc);
            }
        }
        {   // tail
            int rem = cnt - nb;
            int id = (lane < rem) ? g_nbr[off + nb + lane] : 0;
            for (int k = 0; k < rem; k++) {
                int s = __shfl_sync(0xffffffffu, id, k);
                acc = fmaf(__ldg(emb + s * EMB + lane), __ldg(g_dinv + s), acc);
            }
        }
        float a = acc * din;
        float acc0 = sb[lane], acc1 = sb[lane + 32];
#pragma unroll
        for (int c = 0; c < EMB; c++) {
            float ac = __shfl_sync(0xffffffffu, a, c);
            acc0 = fmaf(ac, sW[c * HID + lane], acc0);
            acc1 = fmaf(ac, sW[c * HID + lane + 32], acc1);
        }
        g_s1[node * HID + lane]      = fmaxf(acc0, 0.0f) * din;
        g_s1[node * HID + lane + 32] = fmaxf(acc1, 0.0f) * din;
    }
}

// ---------------- fused GCN layer 2 (gather + matmul) ----------------
#define GB2 512
__global__ void __launch_bounds__(GB2)
k_gcn2(const float* __restrict__ W2, const float* __restrict__ b2) {
    __shared__ float sW[HID * HID];
    __shared__ float sb[HID];
    int tid = threadIdx.x;
    for (int i = tid; i < HID * HID; i += GB2) sW[i] = W2[i];
    if (tid < HID) sb[tid] = b2[tid];
    __syncthreads();

    int warp = tid >> 5, lane = tid & 31;
    int wbase = (blockIdx.x * (GB2 >> 5) + warp) * NPW;
#pragma unroll
    for (int n = 0; n < NPW; n++) {
        int node = wbase + n;
        if (node >= NN) return;
        float din = __ldg(g_dinv + node);
        float a0 = g_s1[node * HID + lane];        // self loop (dinv folded in s1)
        float a1 = g_s1[node * HID + lane + 32];
        int off = g_off[node], cnt = g_cnt[node];
        int nb = cnt & ~31;
        for (int base = 0; base < nb; base += 32) {
            int id = g_nbr[off + base + lane];
#pragma unroll
            for (int k = 0; k < 32; k++) {
                int s = __shfl_sync(0xffffffffu, id, k);
                a0 += __ldg(g_s1 + s * HID + lane);
                a1 += __ldg(g_s1 + s * HID + lane + 32);
            }
        }
        {   // tail
            int rem = cnt - nb;
            int id = (lane < rem) ? g_nbr[off + nb + lane] : 0;
            for (int k = 0; k < rem; k++) {
                int s = __shfl_sync(0xffffffffu, id, k);
                a0 += __ldg(g_s1 + s * HID + lane);
                a1 += __ldg(g_s1 + s * HID + lane + 32);
            }
        }
        a0 *= din; a1 *= din;
        float acc0 = sb[lane], acc1 = sb[lane + 32];
#pragma unroll
        for (int c = 0; c < 32; c++) {
            float ac = __shfl_sync(0xffffffffu, a0, c);
            acc0 = fmaf(ac, sW[c * HID + lane], acc0);
            acc1 = fmaf(ac, sW[c * HID + lane + 32], acc1);
        }
#pragma unroll
        for (int c = 0; c < 32; c++) {
            float ac = __shfl_sync(0xffffffffu, a1, c);
            acc0 = fmaf(ac, sW[(c + 32) * HID + lane], acc0);
            acc1 = fmaf(ac, sW[(c + 32) * HID + lane + 32], acc1);
        }
        g_x2[node * HID + lane]      = acc0;
        g_x2[node * HID + lane + 32] = acc1;
    }
}

// ---------------- final pair MLP ----------------
#define FB 128       // pairs per block (== blockDim)
#define CIN 72       // HID + PATF
#define CPAD 73

__global__ void __launch_bounds__(FB, 4)
k_final(const int* __restrict__ pairs,
        const float* __restrict__ pat,
        const float* __restrict__ Wf1, const float* __restrict__ bf1,
        const float* __restrict__ Wf2, const float* __restrict__ bf2,
        float* __restrict__ out) {
    extern __shared__ float sm[];
    float* sW  = sm;                    // 72*64 = 4608
    float* sb1 = sW + CIN * HID;        // 64
    float* sW2 = sb1 + HID;             // 64
    int*   sp  = (int*)(sW2 + HID);     // 2*FB
    float* sc  = (float*)(sp + 2 * FB); // FB * CPAD

    int tid = threadIdx.x;
    int base = blockIdx.x * FB;

    for (int i = tid; i < CIN * HID; i += FB) sW[i] = Wf1[i];
    if (tid < HID) { sb1[tid] = bf1[tid]; sW2[tid] = Wf2[tid]; }
    {
        int p = base + tid;
        if (p < PPAIR) {
            int2 pr = ((const int2*)pairs)[p];
            sp[2 * tid]     = pr.x;
            sp[2 * tid + 1] = pr.y;
        }
    }
    __syncthreads();

    // stage drug*adr into shared (16 chunk-slots per pair)
    for (int idx = tid; idx < FB * (HID / 4); idx += FB) {
        int pp = idx >> 4, c4 = idx & 15;
        if (base + pp < PPAIR) {
            float4 vd = ((const float4*)g_x2)[sp[2 * pp]     * (HID / 4) + c4];
            float4 va = ((const float4*)g_x2)[sp[2 * pp + 1] * (HID / 4) + c4];
            float* d = sc + pp * CPAD + c4 * 4;
            d[0] = vd.x * va.x; d[1] = vd.y * va.y;
            d[2] = vd.z * va.z; d[3] = vd.w * va.w;
        }
    }
    // stage patient features
    for (int idx = tid; idx < FB * 2; idx += FB) {
        int pp = idx >> 1, h = idx & 1;
        if (base + pp < PPAIR) {
            float4 pv = ((const float4*)pat)[(base + pp) * 2 + h];
            float* d = sc + pp * CPAD + HID + h * 4;
            d[0] = pv.x; d[1] = pv.y; d[2] = pv.z; d[3] = pv.w;
        }
    }
    __syncthreads();

    int p = base + tid;
    if (p >= PPAIR) return;

    unsigned long long acc[HID / 2];
#pragma unroll
    for (int j = 0; j < HID / 2; j++)
        acc[j] = ((const unsigned long long*)sb1)[j];

    const float* c = sc + tid * CPAD;
#pragma unroll 8
    for (int k = 0; k < CIN; k++) {
        unsigned long long ck2 = pack2_dup(c[k]);
        const ulonglong2* wr = (const ulonglong2*)(sW + k * HID);
#pragma unroll
        for (int q = 0; q < HID / 4; q++) {
            ulonglong2 w = wr[q];
            acc[2 * q]     = fma2(ck2, w.x, acc[2 * q]);
            acc[2 * q + 1] = fma2(ck2, w.y, acc[2 * q + 1]);
        }
    }

    float s = bf2[0];
#pragma unroll
    for (int j = 0; j < HID / 2; j++) {
        float2 hv = unpack2(acc[j]);
        s = fmaf(fmaxf(hv.x, 0.0f), sW2[2 * j],     s);
        s = fmaf(fmaxf(hv.y, 0.0f), sW2[2 * j + 1], s);
    }
    out[p] = 1.0f / (1.0f + __expf(-s));
}

// ---------------- launch ----------------
extern "C" void kernel_launch(void* const* d_in, const int* in_sizes, int n_in,
                              void* d_out, int out_size) {
    const int*   edge_index = (const int*)d_in[0];     // (2, E)
    const int*   edge_pairs = (const int*)d_in[1];     // (P, 2)
    const float* pat        = (const float*)d_in[2];   // (P, 8)
    const float* emb        = (const float*)d_in[3];   // (N, 32)
    const float* W1         = (const float*)d_in[4];
    const float* b1         = (const float*)d_in[5];
    const float* W2         = (const float*)d_in[6];
    const float* b2         = (const float*)d_in[7];
    const float* Wf1        = (const float*)d_in[8];
    const float* bf1        = (const float*)d_in[9];
    const float* Wf2        = (const float*)d_in[10];
    const float* bf2        = (const float*)d_in[11];
    float* out = (float*)d_out;

    const int* src = edge_index;
    const int* dst = edge_index + EE;

    // CSR build
    k_zero<<<(NN + 255) / 256, 256>>>();
    k_hist<<<(EE + 255) / 256, 256>>>(dst);
    k_scan1<<<NBLK, SCAN_B>>>();
    k_scan2<<<1, 128>>>();
    k_scan3<<<(NN + 255) / 256, 256>>>();
    k_fill<<<(EE + 255) / 256, 256>>>(src, dst);

    // fused GCN layers (gather + matmul, no float atomics)
    int nodes_per_block = (GB1 >> 5) * NPW;   // 64
    k_gcn1<<<(NN + nodes_per_block - 1) / nodes_per_block, GB1>>>(emb, W1, b1);
    k_gcn2<<<(NN + nodes_per_block - 1) / nodes_per_block, GB2>>>(W2, b2);

    // final pair MLP
    int smem = (CIN * HID + HID + HID) * 4 + 2 * FB * 4 + FB * CPAD * 4;
    cudaFuncSetAttribute(k_final, cudaFuncAttributeMaxDynamicSharedMemorySize, smem);
    k_final<<<(PPAIR + FB - 1) / FB, FB, smem>>>(edge_pairs, pat, Wf1, bf1, Wf2, bf2, out);

    (void)in_sizes; (void)n_in; (void)out_size;
}